// round 4
// baseline (speedup 1.0000x reference)
#include <cuda_runtime.h>
#include <cuda_bf16.h>
#include <cstdint>
#include <math.h>

#define BATCH 8
#define CIN   256
#define COUT  768
#define PADW  36
#define APCH  1296   /* 36*36 */
#define NHEAD 8
#define KP    768    /* split-K': [hi | lo | hi] x 256 */

// ---------------- scratch (device globals; no allocation allowed) ----------
__device__ __align__(16) float g_ap[BATCH * COUT * APCH];       // padded attn
__device__ __align__(16) __nv_bfloat16 g_Wp[COUT * KP];         // W' [o][k']
__device__ __align__(16) __nv_bfloat16 g_Xp[BATCH * 1024 * KP]; // X' [hw][k']
__device__ float g_S1[BATCH * COUT * 25];
__device__ float g_S2[BATCH * COUT * 25];
__device__ float g_Ga[BATCH * 25 * COUT];
__device__ float g_Gb[BATCH * 25 * COUT];

__device__ __forceinline__ uint32_t smem_u32(const void* p) {
    uint32_t a;
    asm("{ .reg .u64 t; cvta.to.shared.u64 t, %1; cvt.u32.u64 %0, t; }" : "=r"(a) : "l"(p));
    return a;
}
#define LDMX4(r0, r1, r2, r3, a) \
    asm volatile("ldmatrix.sync.aligned.m8n8.x4.shared.b16 {%0,%1,%2,%3}, [%4];" \
                 : "=r"(r0), "=r"(r1), "=r"(r2), "=r"(r3) : "r"(a))
#define MMA_BF16(c0, c1, c2, c3, a0, a1, a2, a3, b0, b1) \
    asm volatile("mma.sync.aligned.m16n8k16.row.col.f32.bf16.bf16.f32 " \
                 "{%0,%1,%2,%3}, {%4,%5,%6,%7}, {%8,%9}, {%0,%1,%2,%3};" \
                 : "+f"(c0), "+f"(c1), "+f"(c2), "+f"(c3) \
                 : "r"(a0), "r"(a1), "r"(a2), "r"(a3), "r"(b0), "r"(b1))

// ---------------------------------------------------------------------------
// W' = [hi(w) | lo(w) | hi(w)] per row o.  grid 768 x 256.
__global__ void k_prep_w(const float* __restrict__ w) {
    int idx = blockIdx.x * 256 + threadIdx.x;
    int o = idx >> 8, c = idx & 255;
    float v = w[idx];
    __nv_bfloat16 hi = __float2bfloat16(v);
    __nv_bfloat16 lo = __float2bfloat16(v - __bfloat162float(hi));
    g_Wp[o * KP + c]       = hi;
    g_Wp[o * KP + 256 + c] = lo;
    g_Wp[o * KP + 512 + c] = hi;
}

// X' transposed to [hw][k'] = [hi(x) | hi(x) | lo(x)].  grid (32, BATCH) x 256.
__global__ void k_prep_x(const float* __restrict__ x) {
    __shared__ uint32_t s[32][257];
    int b = blockIdx.y, hw0 = blockIdx.x * 32;
    int tid = threadIdx.x, lane = tid & 31, wp = tid >> 5;
#pragma unroll 4
    for (int it = 0; it < 32; ++it) {
        int c = it * 8 + wp;
        float v = x[(size_t)(b * 256 + c) * 1024 + hw0 + lane];
        __nv_bfloat16 hi = __float2bfloat16(v);
        __nv_bfloat16 lo = __float2bfloat16(v - __bfloat162float(hi));
        s[lane][c] = (uint32_t)__bfloat16_as_ushort(hi)
                   | ((uint32_t)__bfloat16_as_ushort(lo) << 16);
    }
    __syncthreads();
#pragma unroll
    for (int rr = 0; rr < 4; ++rr) {
        int r = wp * 4 + rr;
        __nv_bfloat16* dst = g_Xp + (size_t)(b * 1024 + hw0 + r) * KP;
#pragma unroll
        for (int cb = 0; cb < 4; ++cb) {
            int c0 = cb * 64 + 2 * lane;
            uint32_t u0 = s[r][c0], u1 = s[r][c0 + 1];
            uint32_t hip = (u0 & 0xffffu) | (u1 << 16);
            uint32_t lop = (u0 >> 16) | (u1 & 0xffff0000u);
            *(uint32_t*)(dst + c0)       = hip;
            *(uint32_t*)(dst + 256 + c0) = hip;
            *(uint32_t*)(dst + 512 + c0) = lop;
        }
    }
}

// ---------------------------------------------------------------------------
// Zero the 2-wide padding border of g_ap (interior overwritten by GEMM).
__global__ void k_border() {
    int idx = blockIdx.x * 256 + threadIdx.x;
    if (idx >= BATCH * COUT * APCH) return;
    int cell = idx % APCH;
    int r = cell / PADW, c = cell - r * PADW;
    if (r < 2 || r >= 34 || c < 2 || c >= 34) g_ap[idx] = 0.f;
}

// ---------------------------------------------------------------------------
// bf16 mma.sync GEMM: D[hw, o] = X'[hw,k'] . W'[o,k']^T, tile 128x128, K'=768.
// grid (8 mtiles, 6 ntiles, 8 b), 256 threads (8 warps 2x4).
#define SA 40            /* smem stride in bf16 (80 B) */
#define ABUF(buf) ((buf) * 20480)
#define BBUF(buf) ((buf) * 20480 + 10240)

__global__ __launch_bounds__(256) void k_gemm(const float* __restrict__ bias) {
    __shared__ __align__(16) char sm[41984];
    __shared__ float sbias[128];
    int tid = threadIdx.x, lane = tid & 31, wid = tid >> 5;
    int wm = wid & 1, wn = wid >> 1;
    int m0 = blockIdx.x * 128, n0 = blockIdx.y * 128, b = blockIdx.z;
    uint32_t sbase = smem_u32(sm);

    sbias[tid & 127] = bias[n0 + (tid & 127)];

    const __nv_bfloat16* Xg = g_Xp + (size_t)(b * 1024 + m0) * KP;
    const __nv_bfloat16* Wg = g_Wp + (size_t)n0 * KP;

    float c[4][4][4];
#pragma unroll
    for (int i = 0; i < 4; ++i)
#pragma unroll
        for (int j = 0; j < 4; ++j)
#pragma unroll
            for (int r = 0; r < 4; ++r) c[i][j][r] = 0.f;

    int lrow = tid >> 2, lseg = tid & 3;          // global-load mapping
    uint4 ra[2], rb[2];
#pragma unroll
    for (int j = 0; j < 2; ++j) {
        int row = lrow + j * 64;
        ra[j] = *(const uint4*)(Xg + (size_t)row * KP + lseg * 8);
        rb[j] = *(const uint4*)(Wg + (size_t)row * KP + lseg * 8);
    }

    for (int kc = 0; kc < 24; ++kc) {
        int buf = kc & 1;
        // store staged regs to smem
#pragma unroll
        for (int j = 0; j < 2; ++j) {
            int row = lrow + j * 64;
            uint32_t oa = sbase + ABUF(buf) + row * (SA * 2) + lseg * 16;
            asm volatile("st.shared.v4.b32 [%0], {%1,%2,%3,%4};" ::
                "r"(oa), "r"(ra[j].x), "r"(ra[j].y), "r"(ra[j].z), "r"(ra[j].w) : "memory");
            uint32_t ob = sbase + BBUF(buf) + row * (SA * 2) + lseg * 16;
            asm volatile("st.shared.v4.b32 [%0], {%1,%2,%3,%4};" ::
                "r"(ob), "r"(rb[j].x), "r"(rb[j].y), "r"(rb[j].z), "r"(rb[j].w) : "memory");
        }
        __syncthreads();
        if (kc < 23) {
            int kn = (kc + 1) * 32;
#pragma unroll
            for (int j = 0; j < 2; ++j) {
                int row = lrow + j * 64;
                ra[j] = *(const uint4*)(Xg + (size_t)row * KP + kn + lseg * 8);
                rb[j] = *(const uint4*)(Wg + (size_t)row * KP + kn + lseg * 8);
            }
        }
        // B fragments: 4 n-tiles, k 0..31 (4 regs each)
        uint32_t bf[4][4];
        {
            int q = lane >> 3, ln = lane & 7;
#pragma unroll
            for (int nt = 0; nt < 4; ++nt) {
                uint32_t addr = sbase + BBUF(buf)
                              + (wn * 32 + nt * 8 + ln) * (SA * 2) + q * 16;
                LDMX4(bf[nt][0], bf[nt][1], bf[nt][2], bf[nt][3], addr);
            }
        }
#pragma unroll
        for (int kh = 0; kh < 2; ++kh) {
            uint32_t af[4][4];
            int arow = lane & 15, acol = (lane >> 4);
#pragma unroll
            for (int mt = 0; mt < 4; ++mt) {
                uint32_t addr = sbase + ABUF(buf)
                              + (wm * 64 + mt * 16 + arow) * (SA * 2)
                              + kh * 32 + acol * 16;
                LDMX4(af[mt][0], af[mt][1], af[mt][2], af[mt][3], addr);
            }
#pragma unroll
            for (int mt = 0; mt < 4; ++mt)
#pragma unroll
                for (int nt = 0; nt < 4; ++nt)
                    MMA_BF16(c[mt][nt][0], c[mt][nt][1], c[mt][nt][2], c[mt][nt][3],
                             af[mt][0], af[mt][1], af[mt][2], af[mt][3],
                             bf[nt][kh * 2], bf[nt][kh * 2 + 1]);
        }
        __syncthreads();
    }

    // epilogue: stage 64 o x 128 hw through smem, coalesced float2 stores
    float* sD = (float*)sm;
    float* apb = g_ap + (size_t)b * COUT * APCH;
#pragma unroll 1
    for (int chunk = 0; chunk < 2; ++chunk) {
        if ((wn >> 1) == chunk) {
#pragma unroll
            for (int mt = 0; mt < 4; ++mt)
#pragma unroll
                for (int nt = 0; nt < 4; ++nt) {
                    int ob = (wn & 1) * 32 + nt * 8 + (lane & 3) * 2;
                    int mb = wm * 64 + mt * 16 + (lane >> 2);
                    sD[ob * 132 + mb]           = c[mt][nt][0];
                    sD[(ob + 1) * 132 + mb]     = c[mt][nt][1];
                    sD[ob * 132 + mb + 8]       = c[mt][nt][2];
                    sD[(ob + 1) * 132 + mb + 8] = c[mt][nt][3];
                }
        }
        __syncthreads();
#pragma unroll
        for (int i = 0; i < 16; ++i) {
            int idx = tid + i * 256;          // 0..4095
            int o_loc = idx >> 6, pos = (idx & 63) * 2;
            int o = n0 + chunk * 64 + o_loc;
            int hw = m0 + pos;
            float2 v = *(float2*)&sD[o_loc * 132 + pos];
            float bb = sbias[chunk * 64 + o_loc];
            v.x += bb; v.y += bb;
            *(float2*)&apb[(size_t)o * APCH + ((hw >> 5) + 2) * 36 + (hw & 31) + 2] = v;
        }
        __syncthreads();
    }
}

// ---------------------------------------------------------------------------
// Per (b,o): 25 shifted 32x32 window sums of value and value^2, via row sums.
__global__ void k_stats() {
    __shared__ float tile[APCH];
    __shared__ float rs1[36 * 5], rs2[36 * 5];
    int bo = blockIdx.x, tid = threadIdx.x;
    const float* src = g_ap + (size_t)bo * APCH;
    for (int idx = tid; idx < APCH; idx += 128) tile[idx] = src[idx];
    __syncthreads();
    for (int t = tid; t < 180; t += 128) {
        int r = t / 5, kw = t - r * 5;
        float s = 0.f, s2 = 0.f;
#pragma unroll 8
        for (int c = 0; c < 32; ++c) {
            float v = tile[r * 36 + kw + c];
            s += v; s2 += v * v;
        }
        rs1[t] = s; rs2[t] = s2;
    }
    __syncthreads();
    if (tid < 25) {
        int kh = tid / 5, kw = tid - kh * 5;
        float s = 0.f, s2 = 0.f;
#pragma unroll
        for (int r = 0; r < 32; ++r) {
            s  += rs1[(kh + r) * 5 + kw];
            s2 += rs2[(kh + r) * 5 + kw];
        }
        g_S1[bo * 25 + tid] = s;
        g_S2[bo * 25 + tid] = s2;
    }
}

// ---------------------------------------------------------------------------
__global__ void k_finalize(const float* __restrict__ gn_w, const float* __restrict__ gn_b) {
    int b = blockIdx.x / 25, p = blockIdx.x % 25;
    int o = threadIdx.x;
    float s1 = g_S1[(b * COUT + o) * 25 + p];
    float s2 = g_S2[(b * COUT + o) * 25 + p];
#pragma unroll
    for (int off = 16; off; off >>= 1) {
        s1 += __shfl_xor_sync(0xffffffffu, s1, off);
        s2 += __shfl_xor_sync(0xffffffffu, s2, off);
    }
    float mean = s1 * (1.f / 32768.f);
    float var  = s2 * (1.f / 32768.f) - mean * mean;
    float rstd = rsqrtf(var + 1e-5f);
    float ga = rstd * gn_w[o];
    g_Ga[(b * 25 + p) * COUT + o] = ga;
    g_Gb[(b * 25 + p) * COUT + o] = gn_b[o] - mean * ga;
}

// ---------------------------------------------------------------------------
// Attention: block = (b, n, 4 rows of i), 128 threads (warp=i row, lane=j).
__global__ void k_attn(float* __restrict__ out) {
    __shared__ float sA[25 * 96];
    __shared__ float sB[25 * 96];
    __shared__ float sumB[96];
    __shared__ float qs[32 * 128];
    int tid = threadIdx.x;
    int b = blockIdx.z, n = blockIdx.y;
    for (int idx = tid; idx < 2400; idx += 128) {
        int p = idx / 96, c = idx - p * 96;
        sA[idx] = g_Ga[(b * 25 + p) * COUT + n * 96 + c];
        sB[idx] = g_Gb[(b * 25 + p) * COUT + n * 96 + c];
    }
    __syncthreads();
    if (tid < 96) {
        float s = 0.f;
#pragma unroll
        for (int p = 0; p < 25; ++p) s += sB[p * 96 + tid];
        sumB[tid] = s;
    }
    __syncthreads();
    int warp = tid >> 5, j = tid & 31;
    int i = blockIdx.x * 4 + warp;
    const float* apb = g_ap + ((size_t)(b * COUT) + n * 96) * APCH + i * PADW + j;

#pragma unroll 1
    for (int k = 0; k < 32; ++k) {
        const float* ch = apb + (32 + k) * APCH;
        float s = 0.f;
#pragma unroll
        for (int kh = 0; kh < 5; ++kh)
#pragma unroll
            for (int kw = 0; kw < 5; ++kw)
                s += sA[(kh * 5 + kw) * 96 + 32 + k] * ch[kh * PADW + kw];
        qs[k * 128 + tid] = (s + sumB[32 + k]) * (1.f / 25.f);
    }

    float sal[25];
#pragma unroll
    for (int p = 0; p < 25; ++p) sal[p] = 0.f;
#pragma unroll 1
    for (int k = 0; k < 32; ++k) {
        const float* ch = apb + k * APCH;
        float qk = qs[k * 128 + tid];
#pragma unroll
        for (int kh = 0; kh < 5; ++kh)
#pragma unroll
            for (int kw = 0; kw < 5; ++kw) {
                int p = kh * 5 + kw;
                sal[p] += qk * (sA[p * 96 + k] * ch[kh * PADW + kw] + sB[p * 96 + k]);
            }
    }

    const float scale = 0.17677669529663687f;
    float m = -1e30f;
#pragma unroll
    for (int p = 0; p < 25; ++p) { sal[p] *= scale; m = fmaxf(m, sal[p]); }
    float sum = 0.f;
#pragma unroll
    for (int p = 0; p < 25; ++p) { sal[p] = expf(sal[p] - m); sum += sal[p]; }
    float inv = 1.f / sum;
#pragma unroll
    for (int p = 0; p < 25; ++p) sal[p] *= inv;

    float* ob = out + ((size_t)(b * 256 + n * 32)) * 1024 + i * 32 + j;
#pragma unroll 1
    for (int v = 0; v < 32; ++v) {
        const float* ch = apb + (64 + v) * APCH;
        float s = 0.f;
#pragma unroll
        for (int kh = 0; kh < 5; ++kh)
#pragma unroll
            for (int kw = 0; kw < 5; ++kw) {
                int p = kh * 5 + kw;
                s += sal[p] * (sA[p * 96 + 64 + v] * ch[kh * PADW + kw] + sB[p * 96 + 64 + v]);
            }
        ob[v * 1024] = s;
    }
}

// ---------------------------------------------------------------------------
extern "C" void kernel_launch(void* const* d_in, const int* in_sizes, int n_in,
                              void* d_out, int out_size) {
    (void)in_sizes; (void)n_in; (void)out_size;
    const float* x      = (const float*)d_in[0];
    const float* conv_w = (const float*)d_in[1];
    const float* conv_b = (const float*)d_in[2];
    const float* gn_w   = (const float*)d_in[3];
    const float* gn_b   = (const float*)d_in[4];
    float* out = (float*)d_out;

    k_prep_w<<<768, 256>>>(conv_w);
    k_prep_x<<<dim3(32, BATCH), 256>>>(x);
    int total = BATCH * COUT * APCH;
    k_border<<<(total + 255) / 256, 256>>>();
    k_gemm<<<dim3(8, 6, BATCH), 256>>>(conv_b);
    k_stats<<<BATCH * COUT, 128>>>();
    k_finalize<<<BATCH * 25, 768>>>(gn_w, gn_b);
    k_attn<<<dim3(8, NHEAD, BATCH), 128>>>(out);
}

// round 5
// speedup vs baseline: 1.0045x; 1.0045x over previous
#include <cuda_runtime.h>
#include <cuda_bf16.h>
#include <cstdint>
#include <math.h>

#define BATCH 8
#define CIN   256
#define COUT  768
#define PADW  36
#define APCH  1296   /* 36*36 */
#define NHEAD 8
#define KP    768    /* split-K': [hi | lo | hi] x 256 */

// ---------------- scratch (device globals; no allocation allowed) ----------
__device__ __align__(16) float g_ap[BATCH * COUT * APCH];       // padded attn
__device__ __align__(16) __nv_bfloat16 g_Wp[COUT * KP];         // W' [o][k']
__device__ __align__(16) __nv_bfloat16 g_Xp[BATCH * 1024 * KP]; // X' [hw][k']
__device__ float g_S1[BATCH * COUT * 25];
__device__ float g_S2[BATCH * COUT * 25];
__device__ float g_Ga[BATCH * 25 * COUT];
__device__ float g_Gb[BATCH * 25 * COUT];

__device__ __forceinline__ uint32_t smem_u32(const void* p) {
    uint32_t a;
    asm("{ .reg .u64 t; cvta.to.shared.u64 t, %1; cvt.u32.u64 %0, t; }" : "=r"(a) : "l"(p));
    return a;
}
#define LDMX4(r0, r1, r2, r3, a) \
    asm volatile("ldmatrix.sync.aligned.m8n8.x4.shared.b16 {%0,%1,%2,%3}, [%4];" \
                 : "=r"(r0), "=r"(r1), "=r"(r2), "=r"(r3) : "r"(a))
#define MMA_BF16(c0, c1, c2, c3, a0, a1, a2, a3, b0, b1) \
    asm volatile("mma.sync.aligned.m16n8k16.row.col.f32.bf16.bf16.f32 " \
                 "{%0,%1,%2,%3}, {%4,%5,%6,%7}, {%8,%9}, {%0,%1,%2,%3};" \
                 : "+f"(c0), "+f"(c1), "+f"(c2), "+f"(c3) \
                 : "r"(a0), "r"(a1), "r"(a2), "r"(a3), "r"(b0), "r"(b1))

// ---------------------------------------------------------------------------
// W' = [hi(w) | lo(w) | hi(w)] per row o.  grid 768 x 256.
__global__ void k_prep_w(const float* __restrict__ w) {
    int idx = blockIdx.x * 256 + threadIdx.x;
    int o = idx >> 8, c = idx & 255;
    float v = w[idx];
    __nv_bfloat16 hi = __float2bfloat16(v);
    __nv_bfloat16 lo = __float2bfloat16(v - __bfloat162float(hi));
    g_Wp[o * KP + c]       = hi;
    g_Wp[o * KP + 256 + c] = lo;
    g_Wp[o * KP + 512 + c] = hi;
}

// X' transposed to [hw][k'] = [hi(x) | hi(x) | lo(x)].  grid (32, BATCH) x 256.
__global__ void k_prep_x(const float* __restrict__ x) {
    __shared__ uint32_t s[32][257];
    int b = blockIdx.y, hw0 = blockIdx.x * 32;
    int tid = threadIdx.x, lane = tid & 31, wp = tid >> 5;
#pragma unroll 4
    for (int it = 0; it < 32; ++it) {
        int c = it * 8 + wp;
        float v = x[(size_t)(b * 256 + c) * 1024 + hw0 + lane];
        __nv_bfloat16 hi = __float2bfloat16(v);
        __nv_bfloat16 lo = __float2bfloat16(v - __bfloat162float(hi));
        s[lane][c] = (uint32_t)__bfloat16_as_ushort(hi)
                   | ((uint32_t)__bfloat16_as_ushort(lo) << 16);
    }
    __syncthreads();
#pragma unroll
    for (int rr = 0; rr < 4; ++rr) {
        int r = wp * 4 + rr;
        __nv_bfloat16* dst = g_Xp + (size_t)(b * 1024 + hw0 + r) * KP;
#pragma unroll
        for (int cb = 0; cb < 4; ++cb) {
            int c0 = cb * 64 + 2 * lane;
            uint32_t u0 = s[r][c0], u1 = s[r][c0 + 1];
            uint32_t hip = (u0 & 0xffffu) | (u1 << 16);
            uint32_t lop = (u0 >> 16) | (u1 & 0xffff0000u);
            *(uint32_t*)(dst + c0)       = hip;
            *(uint32_t*)(dst + 256 + c0) = hip;
            *(uint32_t*)(dst + 512 + c0) = lop;
        }
    }
}

// ---------------------------------------------------------------------------
// Zero the 2-wide padding border of g_ap (interior overwritten by GEMM).
__global__ void k_border() {
    int idx = blockIdx.x * 256 + threadIdx.x;
    if (idx >= BATCH * COUT * APCH) return;
    int cell = idx % APCH;
    int r = cell / PADW, c = cell - r * PADW;
    if (r < 2 || r >= 34 || c < 2 || c >= 34) g_ap[idx] = 0.f;
}

// ---------------------------------------------------------------------------
// bf16 mma.sync GEMM: D[hw, o] = X'[hw,k'] . W'[o,k']^T, tile 128x128, K'=768.
// grid (8 mtiles, 6 ntiles, 8 b), 256 threads (8 warps 2x4).
#define SA 40            /* smem stride in bf16 (80 B) */
#define ABUF(buf) ((buf) * 20480)
#define BBUF(buf) ((buf) * 20480 + 10240)

__global__ __launch_bounds__(256) void k_gemm(const float* __restrict__ bias) {
    __shared__ __align__(16) char sm[41984];
    __shared__ float sbias[128];
    int tid = threadIdx.x, lane = tid & 31, wid = tid >> 5;
    int wm = wid & 1, wn = wid >> 1;
    int m0 = blockIdx.x * 128, n0 = blockIdx.y * 128, b = blockIdx.z;
    uint32_t sbase = smem_u32(sm);

    sbias[tid & 127] = bias[n0 + (tid & 127)];

    const __nv_bfloat16* Xg = g_Xp + (size_t)(b * 1024 + m0) * KP;
    const __nv_bfloat16* Wg = g_Wp + (size_t)n0 * KP;

    float c[4][4][4];
#pragma unroll
    for (int i = 0; i < 4; ++i)
#pragma unroll
        for (int j = 0; j < 4; ++j)
#pragma unroll
            for (int r = 0; r < 4; ++r) c[i][j][r] = 0.f;

    int lrow = tid >> 2, lseg = tid & 3;          // global-load mapping
    uint4 ra[2], rb[2];
#pragma unroll
    for (int j = 0; j < 2; ++j) {
        int row = lrow + j * 64;
        ra[j] = *(const uint4*)(Xg + (size_t)row * KP + lseg * 8);
        rb[j] = *(const uint4*)(Wg + (size_t)row * KP + lseg * 8);
    }

    for (int kc = 0; kc < 24; ++kc) {
        int buf = kc & 1;
        // store staged regs to smem
#pragma unroll
        for (int j = 0; j < 2; ++j) {
            int row = lrow + j * 64;
            uint32_t oa = sbase + ABUF(buf) + row * (SA * 2) + lseg * 16;
            asm volatile("st.shared.v4.b32 [%0], {%1,%2,%3,%4};" ::
                "r"(oa), "r"(ra[j].x), "r"(ra[j].y), "r"(ra[j].z), "r"(ra[j].w) : "memory");
            uint32_t ob = sbase + BBUF(buf) + row * (SA * 2) + lseg * 16;
            asm volatile("st.shared.v4.b32 [%0], {%1,%2,%3,%4};" ::
                "r"(ob), "r"(rb[j].x), "r"(rb[j].y), "r"(rb[j].z), "r"(rb[j].w) : "memory");
        }
        __syncthreads();
        if (kc < 23) {
            int kn = (kc + 1) * 32;
#pragma unroll
            for (int j = 0; j < 2; ++j) {
                int row = lrow + j * 64;
                ra[j] = *(const uint4*)(Xg + (size_t)row * KP + kn + lseg * 8);
                rb[j] = *(const uint4*)(Wg + (size_t)row * KP + kn + lseg * 8);
            }
        }
        // B fragments: 4 n-tiles, k 0..31 (4 regs each)
        uint32_t bf[4][4];
        {
            int q = lane >> 3, ln = lane & 7;
#pragma unroll
            for (int nt = 0; nt < 4; ++nt) {
                uint32_t addr = sbase + BBUF(buf)
                              + (wn * 32 + nt * 8 + ln) * (SA * 2) + q * 16;
                LDMX4(bf[nt][0], bf[nt][1], bf[nt][2], bf[nt][3], addr);
            }
        }
#pragma unroll
        for (int kh = 0; kh < 2; ++kh) {
            uint32_t af[4][4];
            int arow = lane & 15, acol = (lane >> 4);
#pragma unroll
            for (int mt = 0; mt < 4; ++mt) {
                uint32_t addr = sbase + ABUF(buf)
                              + (wm * 64 + mt * 16 + arow) * (SA * 2)
                              + kh * 32 + acol * 16;
                LDMX4(af[mt][0], af[mt][1], af[mt][2], af[mt][3], addr);
            }
#pragma unroll
            for (int mt = 0; mt < 4; ++mt)
#pragma unroll
                for (int nt = 0; nt < 4; ++nt)
                    MMA_BF16(c[mt][nt][0], c[mt][nt][1], c[mt][nt][2], c[mt][nt][3],
                             af[mt][0], af[mt][1], af[mt][2], af[mt][3],
                             bf[nt][kh * 2], bf[nt][kh * 2 + 1]);
        }
        __syncthreads();
    }

    // epilogue: stage 64 o x 128 hw through smem, coalesced float2 stores
    float* sD = (float*)sm;
    float* apb = g_ap + (size_t)b * COUT * APCH;
#pragma unroll 1
    for (int chunk = 0; chunk < 2; ++chunk) {
        if ((wn >> 1) == chunk) {
#pragma unroll
            for (int mt = 0; mt < 4; ++mt)
#pragma unroll
                for (int nt = 0; nt < 4; ++nt) {
                    int ob = (wn & 1) * 32 + nt * 8 + (lane & 3) * 2;
                    int mb = wm * 64 + mt * 16 + (lane >> 2);
                    sD[ob * 132 + mb]           = c[mt][nt][0];
                    sD[(ob + 1) * 132 + mb]     = c[mt][nt][1];
                    sD[ob * 132 + mb + 8]       = c[mt][nt][2];
                    sD[(ob + 1) * 132 + mb + 8] = c[mt][nt][3];
                }
        }
        __syncthreads();
#pragma unroll
        for (int i = 0; i < 16; ++i) {
            int idx = tid + i * 256;          // 0..4095
            int o_loc = idx >> 6, pos = (idx & 63) * 2;
            int o = n0 + chunk * 64 + o_loc;
            int hw = m0 + pos;
            float2 v = *(float2*)&sD[o_loc * 132 + pos];
            float bb = sbias[chunk * 64 + o_loc];
            v.x += bb; v.y += bb;
            *(float2*)&apb[(size_t)o * APCH + ((hw >> 5) + 2) * 36 + (hw & 31) + 2] = v;
        }
        __syncthreads();
    }
}

// ---------------------------------------------------------------------------
// Per (b,o): 25 shifted 32x32 window sums of value and value^2, via row sums.
__global__ void k_stats() {
    __shared__ float tile[APCH];
    __shared__ float rs1[36 * 5], rs2[36 * 5];
    int bo = blockIdx.x, tid = threadIdx.x;
    const float* src = g_ap + (size_t)bo * APCH;
    for (int idx = tid; idx < APCH; idx += 128) tile[idx] = src[idx];
    __syncthreads();
    for (int t = tid; t < 180; t += 128) {
        int r = t / 5, kw = t - r * 5;
        float s = 0.f, s2 = 0.f;
#pragma unroll 8
        for (int c = 0; c < 32; ++c) {
            float v = tile[r * 36 + kw + c];
            s += v; s2 += v * v;
        }
        rs1[t] = s; rs2[t] = s2;
    }
    __syncthreads();
    if (tid < 25) {
        int kh = tid / 5, kw = tid - kh * 5;
        float s = 0.f, s2 = 0.f;
#pragma unroll
        for (int r = 0; r < 32; ++r) {
            s  += rs1[(kh + r) * 5 + kw];
            s2 += rs2[(kh + r) * 5 + kw];
        }
        g_S1[bo * 25 + tid] = s;
        g_S2[bo * 25 + tid] = s2;
    }
}

// ---------------------------------------------------------------------------
__global__ void k_finalize(const float* __restrict__ gn_w, const float* __restrict__ gn_b) {
    int b = blockIdx.x / 25, p = blockIdx.x % 25;
    int o = threadIdx.x;
    float s1 = g_S1[(b * COUT + o) * 25 + p];
    float s2 = g_S2[(b * COUT + o) * 25 + p];
#pragma unroll
    for (int off = 16; off; off >>= 1) {
        s1 += __shfl_xor_sync(0xffffffffu, s1, off);
        s2 += __shfl_xor_sync(0xffffffffu, s2, off);
    }
    float mean = s1 * (1.f / 32768.f);
    float var  = s2 * (1.f / 32768.f) - mean * mean;
    float rstd = rsqrtf(var + 1e-5f);
    float ga = rstd * gn_w[o];
    g_Ga[(b * 25 + p) * COUT + o] = ga;
    g_Gb[(b * 25 + p) * COUT + o] = gn_b[o] - mean * ga;
}

// ---------------------------------------------------------------------------
// Attention: block = (b, n, 4 rows of i), 128 threads (warp=i row, lane=j).
__global__ void k_attn(float* __restrict__ out) {
    __shared__ float sA[25 * 96];
    __shared__ float sB[25 * 96];
    __shared__ float sumB[96];
    __shared__ float qs[32 * 128];
    int tid = threadIdx.x;
    int b = blockIdx.z, n = blockIdx.y;
    for (int idx = tid; idx < 2400; idx += 128) {
        int p = idx / 96, c = idx - p * 96;
        sA[idx] = g_Ga[(b * 25 + p) * COUT + n * 96 + c];
        sB[idx] = g_Gb[(b * 25 + p) * COUT + n * 96 + c];
    }
    __syncthreads();
    if (tid < 96) {
        float s = 0.f;
#pragma unroll
        for (int p = 0; p < 25; ++p) s += sB[p * 96 + tid];
        sumB[tid] = s;
    }
    __syncthreads();
    int warp = tid >> 5, j = tid & 31;
    int i = blockIdx.x * 4 + warp;
    const float* apb = g_ap + ((size_t)(b * COUT) + n * 96) * APCH + i * PADW + j;

#pragma unroll 1
    for (int k = 0; k < 32; ++k) {
        const float* ch = apb + (32 + k) * APCH;
        float s = 0.f;
#pragma unroll
        for (int kh = 0; kh < 5; ++kh)
#pragma unroll
            for (int kw = 0; kw < 5; ++kw)
                s += sA[(kh * 5 + kw) * 96 + 32 + k] * ch[kh * PADW + kw];
        qs[k * 128 + tid] = (s + sumB[32 + k]) * (1.f / 25.f);
    }

    float sal[25];
#pragma unroll
    for (int p = 0; p < 25; ++p) sal[p] = 0.f;
#pragma unroll 1
    for (int k = 0; k < 32; ++k) {
        const float* ch = apb + k * APCH;
        float qk = qs[k * 128 + tid];
#pragma unroll
        for (int kh = 0; kh < 5; ++kh)
#pragma unroll
            for (int kw = 0; kw < 5; ++kw) {
                int p = kh * 5 + kw;
                sal[p] += qk * (sA[p * 96 + k] * ch[kh * PADW + kw] + sB[p * 96 + k]);
            }
    }

    const float scale = 0.17677669529663687f;
    float m = -1e30f;
#pragma unroll
    for (int p = 0; p < 25; ++p) { sal[p] *= scale; m = fmaxf(m, sal[p]); }
    float sum = 0.f;
#pragma unroll
    for (int p = 0; p < 25; ++p) { sal[p] = expf(sal[p] - m); sum += sal[p]; }
    float inv = 1.f / sum;
#pragma unroll
    for (int p = 0; p < 25; ++p) sal[p] *= inv;

    float* ob = out + ((size_t)(b * 256 + n * 32)) * 1024 + i * 32 + j;
#pragma unroll 1
    for (int v = 0; v < 32; ++v) {
        const float* ch = apb + (64 + v) * APCH;
        float s = 0.f;
#pragma unroll
        for (int kh = 0; kh < 5; ++kh)
#pragma unroll
            for (int kw = 0; kw < 5; ++kw) {
                int p = kh * 5 + kw;
                s += sal[p] * (sA[p * 96 + 64 + v] * ch[kh * PADW + kw] + sB[p * 96 + 64 + v]);
            }
        ob[v * 1024] = s;
    }
}

// ---------------------------------------------------------------------------
extern "C" void kernel_launch(void* const* d_in, const int* in_sizes, int n_in,
                              void* d_out, int out_size) {
    (void)in_sizes; (void)n_in; (void)out_size;
    const float* x      = (const float*)d_in[0];
    const float* conv_w = (const float*)d_in[1];
    const float* conv_b = (const float*)d_in[2];
    const float* gn_w   = (const float*)d_in[3];
    const float* gn_b   = (const float*)d_in[4];
    float* out = (float*)d_out;

    k_prep_w<<<768, 256>>>(conv_w);
    k_prep_x<<<dim3(32, BATCH), 256>>>(x);
    int total = BATCH * COUT * APCH;
    k_border<<<(total + 255) / 256, 256>>>();
    k_gemm<<<dim3(8, 6, BATCH), 256>>>(conv_b);
    k_stats<<<BATCH * COUT, 128>>>();
    k_finalize<<<BATCH * 25, 768>>>(gn_w, gn_b);
    k_attn<<<dim3(8, NHEAD, BATCH), 128>>>(out);
}